// round 2
// baseline (speedup 1.0000x reference)
#include <cuda_runtime.h>
#include <cuda_fp16.h>
#include <cstdint>

#define THREADS 256
#define MT      64
#define EMBED   512
#define KQ1     1024
#define ROWS    32768
#define NTILES  (ROWS / MT)     // 512
#define GRID    148
#define KC      64

#define A_BLK   8192            // 64 rows * 128B (64 fp16 k)
#define B_BLK   65536           // 512 rows * 128B
#define XTILE   (MT * KQ1 * 2)  // 131072 bytes per 64-row X tile

// smem layout (bytes)
#define SM_H    0                       // 64KB: h1 tile, blocked [kblk][row][kk]
#define SM_A    (SM_H + 65536)          // 2 x 8KB A staging
#define SM_B    (SM_A + 2 * A_BLK)      // 2 x 64KB B staging
#define SM_QS   SM_A                    // reuse A staging: float qs[8][64] (2KB)
#define SMEM_TOTAL (SM_B + 2 * B_BLK)   // 212992

// ---------------- device global scratch --------------------------------------
__device__ __align__(128) __half g_Xh [(size_t)ROWS * KQ1];    // X, A-layout fp16
__device__ __align__(128) __half g_W1Q[(size_t)EMBED * KQ1];   // weights, B-layout [N][K]
__device__ __align__(128) __half g_W2Q[(size_t)EMBED * EMBED];
__device__ __align__(128) __half g_W1V[(size_t)EMBED * EMBED];
__device__ __align__(128) __half g_W2V[(size_t)EMBED * EMBED];

// ---------------- helpers -----------------------------------------------------
__device__ __forceinline__ uint32_t swz(uint32_t b) { return b ^ ((b >> 3) & 0x70); }

__device__ __forceinline__ uint32_t smem_u32(const void* p) {
    uint32_t a;
    asm("{ .reg .u64 t; cvta.to.shared.u64 t, %1; cvt.u32.u64 %0, t; }" : "=r"(a) : "l"(p));
    return a;
}

__device__ __forceinline__ void cp16(uint32_t dst, const void* src) {
    asm volatile("cp.async.cg.shared.global [%0], [%1], 16;" :: "r"(dst), "l"(src));
}
#define CP_COMMIT() asm volatile("cp.async.commit_group;")
#define CP_WAIT(n)  asm volatile("cp.async.wait_group %0;" :: "n"(n))

__device__ __forceinline__ void ldsm4(uint32_t& r0, uint32_t& r1, uint32_t& r2, uint32_t& r3,
                                      uint32_t addr) {
    asm volatile("ldmatrix.sync.aligned.m8n8.x4.shared.b16 {%0,%1,%2,%3}, [%4];"
                 : "=r"(r0), "=r"(r1), "=r"(r2), "=r"(r3) : "r"(addr));
}

__device__ __forceinline__ void mma16816(float* c, const uint32_t* a, const uint32_t* b) {
    asm volatile(
        "mma.sync.aligned.m16n8k16.row.col.f32.f16.f16.f32 "
        "{%0,%1,%2,%3}, {%4,%5,%6,%7}, {%8,%9}, {%0,%1,%2,%3};"
        : "+f"(c[0]), "+f"(c[1]), "+f"(c[2]), "+f"(c[3])
        : "r"(a[0]), "r"(a[1]), "r"(a[2]), "r"(a[3]), "r"(b[0]), "r"(b[1]));
}

// ---------------- prep kernels ------------------------------------------------
// Weights: W[K][N] fp32 row-major -> B-layout fp16: block b=k/64,
// byte = b*B_BLK + swz(n*128 + (k%64)*2)
__global__ void prep_weights(const float* __restrict__ Qw1, const float* __restrict__ Qw2,
                             const float* __restrict__ Vw1, const float* __restrict__ Vw2) {
    size_t idx = (size_t)blockIdx.x * blockDim.x + threadIdx.x;
    const float* src; __half* dst;
    size_t off = idx;
    if (off < (size_t)KQ1 * EMBED) { src = Qw1; dst = g_W1Q; }
    else {
        off -= (size_t)KQ1 * EMBED;
        if (off < (size_t)EMBED * EMBED) { src = Qw2; dst = g_W2Q; }
        else {
            off -= (size_t)EMBED * EMBED;
            if (off < (size_t)EMBED * EMBED) { src = Vw1; dst = g_W1V; }
            else {
                off -= (size_t)EMBED * EMBED;
                if (off >= (size_t)EMBED * EMBED) return;
                src = Vw2; dst = g_W2V;
            }
        }
    }
    size_t k = off / EMBED, n = off % EMBED;
    float v = src[k * EMBED + n];
    size_t b = k >> 6; uint32_t kk = (uint32_t)(k & 63);
    char* p = (char*)dst + b * (size_t)B_BLK + swz((uint32_t)(n * 128 + kk * 2));
    *(__half*)p = __float2half_rn(v);
}

// X = concat(states, actions) -> A-layout fp16, MT=64-row tiles, K64 blocks
__global__ void prep_x(const float* __restrict__ states, const float* __restrict__ actions) {
    size_t idx = (size_t)blockIdx.x * blockDim.x + threadIdx.x;  // ROWS*512 half2 pairs
    if (idx >= (size_t)ROWS * 512) return;
    size_t r = idx >> 9;
    int k = ((int)(idx & 511)) * 2;
    float2 v;
    if (k < 512) v = *(const float2*)(states + r * 512 + k);
    else         v = *(const float2*)(actions + r * 512 + (k - 512));
    __half2 h = __floats2half2_rn(v.x, v.y);
    size_t t = r >> 6; int rr = (int)(r & 63);
    int b = k >> 6, kk = k & 63;
    char* p = (char*)g_Xh + t * (size_t)XTILE + (size_t)b * A_BLK
              + swz((uint32_t)(rr * 128 + kk * 2));
    *(__half2*)p = h;
}

// ---------------- main-kernel building blocks ---------------------------------
// Compute one K64 chunk: A block 64x64 at a_base, B block 512x64 at b_base.
// acc[i][j][*]: warp tile M64 x N64, i = m16 block, j = n8 block.
__device__ __forceinline__ void compute_chunk(uint32_t a_base, uint32_t b_base,
                                              float acc[4][8][4], int lane, int nbase) {
    int l16 = lane & 15;
    int ahalf = (lane >= 16) ? 8 : 0;
    int l8 = lane & 7;
    int q  = lane >> 3;                 // 0..3
    int bn = ((q >= 2) ? 8 : 0) + l8;
    int bk = (q & 1) ? 8 : 0;
    #pragma unroll
    for (int s = 0; s < 4; s++) {
        uint32_t a[4][4];
        #pragma unroll
        for (int i = 0; i < 4; i++) {
            int row = i * 16 + l16;
            int col = s * 16 + ahalf;
            ldsm4(a[i][0], a[i][1], a[i][2], a[i][3], a_base + swz(row * 128 + col * 2));
        }
        uint32_t b[4][4];
        #pragma unroll
        for (int p = 0; p < 4; p++) {
            int n = nbase + p * 16 + bn;
            int k = s * 16 + bk;
            ldsm4(b[p][0], b[p][1], b[p][2], b[p][3], b_base + swz(n * 128 + k * 2));
        }
        #pragma unroll
        for (int i = 0; i < 4; i++)
            #pragma unroll
            for (int j = 0; j < 8; j++)
                mma16816(acc[i][j], a[i], &b[j >> 1][(j & 1) * 2]);
    }
}

// GEMM with A streamed from global (X tiles) + B streamed (weights), double-buffered.
__device__ void gemm_staged(const char* __restrict__ Ag, const char* __restrict__ Bg, int nkb,
                            uint32_t sb, float acc[4][8][4], int tid, int lane, int nbase) {
    for (int i = tid; i < 512; i += THREADS)  cp16(sb + SM_A + i * 16, Ag + i * 16);
    for (int i = tid; i < 4096; i += THREADS) cp16(sb + SM_B + i * 16, Bg + i * 16);
    CP_COMMIT();
    for (int kb = 0; kb < nkb; kb++) {
        int cur = kb & 1;
        if (kb + 1 < nkb) {
            int nxt = cur ^ 1;
            const char* a = Ag + (size_t)(kb + 1) * A_BLK;
            const char* b = Bg + (size_t)(kb + 1) * B_BLK;
            for (int i = tid; i < 512; i += THREADS)  cp16(sb + SM_A + nxt * A_BLK + i * 16, a + i * 16);
            for (int i = tid; i < 4096; i += THREADS) cp16(sb + SM_B + nxt * B_BLK + i * 16, b + i * 16);
            CP_COMMIT();
            CP_WAIT(1);
        } else {
            CP_WAIT(0);
        }
        __syncthreads();
        compute_chunk(sb + SM_A + cur * A_BLK, sb + SM_B + cur * B_BLK, acc, lane, nbase);
        __syncthreads();
    }
}

// GEMM with A = h1 resident in smem (SM_H blocks), B streamed.
__device__ void gemm_smemA(const char* __restrict__ Bg, int nkb, uint32_t sb,
                           float acc[4][8][4], int tid, int lane, int nbase) {
    for (int i = tid; i < 4096; i += THREADS) cp16(sb + SM_B + i * 16, Bg + i * 16);
    CP_COMMIT();
    for (int kb = 0; kb < nkb; kb++) {
        int cur = kb & 1;
        if (kb + 1 < nkb) {
            int nxt = cur ^ 1;
            const char* b = Bg + (size_t)(kb + 1) * B_BLK;
            for (int i = tid; i < 4096; i += THREADS) cp16(sb + SM_B + nxt * B_BLK + i * 16, b + i * 16);
            CP_COMMIT();
            CP_WAIT(1);
        } else {
            CP_WAIT(0);
        }
        __syncthreads();
        compute_chunk(sb + SM_H + kb * A_BLK, sb + SM_B + cur * B_BLK, acc, lane, nbase);
        __syncthreads();
    }
}

// bias + relu -> h (fp16) into smem H (blocked layout for next layer's A)
__device__ void epi_mid(float acc[4][8][4], const float* __restrict__ bias,
                        char* __restrict__ smem, int lane, int warp) {
    int g = lane >> 2, tig = lane & 3;
    #pragma unroll
    for (int j = 0; j < 8; j++) {
        int c = warp * 64 + j * 8 + tig * 2;
        float b0 = bias[c], b1 = bias[c + 1];
        int blk = c >> 6, kk = c & 63;
        char* base = smem + SM_H + blk * A_BLK;
        #pragma unroll
        for (int i = 0; i < 4; i++) {
            float v0 = fmaxf(acc[i][j][0] + b0, 0.f);
            float v1 = fmaxf(acc[i][j][1] + b1, 0.f);
            float v2 = fmaxf(acc[i][j][2] + b0, 0.f);
            float v3 = fmaxf(acc[i][j][3] + b1, 0.f);
            int r0 = i * 16 + g, r1 = r0 + 8;
            *(__half2*)(base + swz((uint32_t)(r0 * 128 + kk * 2))) = __floats2half2_rn(v0, v1);
            *(__half2*)(base + swz((uint32_t)(r1 * 128 + kk * 2))) = __floats2half2_rn(v2, v3);
        }
    }
}

// bias + relu + dot(w3) + b3 -> out[64]
__device__ void epi_fin(float acc[4][8][4], const float* __restrict__ bias,
                        const float* __restrict__ w3, const float* __restrict__ b3g,
                        char* __restrict__ smem, float* __restrict__ outp,
                        int lane, int warp, int tid) {
    int g = lane >> 2, tig = lane & 3;
    float p[8];
    #pragma unroll
    for (int k = 0; k < 8; k++) p[k] = 0.f;
    #pragma unroll
    for (int j = 0; j < 8; j++) {
        int c = warp * 64 + j * 8 + tig * 2;
        float b0 = bias[c], b1 = bias[c + 1];
        float w0 = w3[c],  w1 = w3[c + 1];
        #pragma unroll
        for (int i = 0; i < 4; i++) {
            p[i * 2 + 0] += fmaxf(acc[i][j][0] + b0, 0.f) * w0 + fmaxf(acc[i][j][1] + b1, 0.f) * w1;
            p[i * 2 + 1] += fmaxf(acc[i][j][2] + b0, 0.f) * w0 + fmaxf(acc[i][j][3] + b1, 0.f) * w1;
        }
    }
    #pragma unroll
    for (int k = 0; k < 8; k++) {
        p[k] += __shfl_xor_sync(0xffffffffu, p[k], 1);
        p[k] += __shfl_xor_sync(0xffffffffu, p[k], 2);
    }
    float* qs = (float*)(smem + SM_QS);
    if (tig == 0) {
        #pragma unroll
        for (int i = 0; i < 4; i++) {
            qs[warp * 64 + i * 16 + g]     = p[i * 2 + 0];
            qs[warp * 64 + i * 16 + g + 8] = p[i * 2 + 1];
        }
    }
    __syncthreads();
    if (tid < 64) {
        float s = b3g[0];
        #pragma unroll
        for (int w = 0; w < 8; w++) s += qs[w * 64 + tid];
        outp[tid] = s;
    }
    __syncthreads();
}

__device__ __forceinline__ void zero_acc(float acc[4][8][4]) {
    #pragma unroll
    for (int i = 0; i < 4; i++)
        #pragma unroll
        for (int j = 0; j < 8; j++)
            #pragma unroll
            for (int e = 0; e < 4; e++) acc[i][j][e] = 0.f;
}

// ---------------- fused main kernel -------------------------------------------
__global__ void __launch_bounds__(THREADS, 1)
fused_mlp(const float* __restrict__ b1Q, const float* __restrict__ b2Q,
          const float* __restrict__ w3Q, const float* __restrict__ b3Q,
          const float* __restrict__ b1V, const float* __restrict__ b2V,
          const float* __restrict__ w3V, const float* __restrict__ b3V,
          float* __restrict__ out) {
    extern __shared__ __align__(1024) char smem[];
    uint32_t sb = smem_u32(smem);
    int tid = threadIdx.x, lane = tid & 31, warp = tid >> 5;
    int nbase = warp * 64;

    for (int t = blockIdx.x; t < NTILES; t += GRID) {
        const char* Xt = (const char*)g_Xh + (size_t)t * XTILE;
        float acc[4][8][4];

        // ---- Q network ----
        zero_acc(acc);
        gemm_staged(Xt, (const char*)g_W1Q, 16, sb, acc, tid, lane, nbase);
        epi_mid(acc, b1Q, smem, lane, warp);
        __syncthreads();
        zero_acc(acc);
        gemm_smemA((const char*)g_W2Q, 8, sb, acc, tid, lane, nbase);
        epi_fin(acc, b2Q, w3Q, b3Q, smem, out + (size_t)t * MT, lane, warp, tid);

        // ---- V network (states only = first 8 K-blocks of X) ----
        zero_acc(acc);
        gemm_staged(Xt, (const char*)g_W1V, 8, sb, acc, tid, lane, nbase);
        epi_mid(acc, b1V, smem, lane, warp);
        __syncthreads();
        zero_acc(acc);
        gemm_smemA((const char*)g_W2V, 8, sb, acc, tid, lane, nbase);
        epi_fin(acc, b2V, w3V, b3V, smem, out + ROWS + (size_t)t * MT, lane, warp, tid);
    }
}

// ---------------- launch -------------------------------------------------------
extern "C" void kernel_launch(void* const* d_in, const int* in_sizes, int n_in,
                              void* d_out, int out_size) {
    const float* states  = (const float*)d_in[0];
    const float* actions = (const float*)d_in[1];
    const float* Qw1 = (const float*)d_in[2];  const float* Qb1 = (const float*)d_in[3];
    const float* Qw2 = (const float*)d_in[4];  const float* Qb2 = (const float*)d_in[5];
    const float* Qw3 = (const float*)d_in[6];  const float* Qb3 = (const float*)d_in[7];
    const float* Vw1 = (const float*)d_in[8];  const float* Vb1 = (const float*)d_in[9];
    const float* Vw2 = (const float*)d_in[10]; const float* Vb2 = (const float*)d_in[11];
    const float* Vw3 = (const float*)d_in[12]; const float* Vb3 = (const float*)d_in[13];
    float* out = (float*)d_out;

    cudaFuncSetAttribute(fused_mlp, cudaFuncAttributeMaxDynamicSharedMemorySize, SMEM_TOTAL);

    prep_weights<<<5120, 256>>>(Qw1, Qw2, Vw1, Vw2);
    prep_x<<<65536, 256>>>(states, actions);
    fused_mlp<<<GRID, THREADS, SMEM_TOTAL>>>(Qb1, Qb2, Qw3, Qb3, Vb1, Vb2, Vw3, Vb3, out);
}

// round 5
// speedup vs baseline: 1.0343x; 1.0343x over previous
#include <cuda_runtime.h>
#include <cuda_fp16.h>
#include <cstdint>

#define THREADS 256
#define MT      128
#define EMBED   512
#define KQ1     1024
#define ROWS    32768
#define NTILES  (ROWS / MT)     // 256
#define GRID    148

#define A_BLK   16384           // 128 rows * 128B (64 fp16 k)
#define B_BLKF  65536           // full K64 weight block (512 n-rows) in global
#define B_SL    32768           // 256 n-row pass slice
#define XTILE   (MT * KQ1 * 2)  // 262144 bytes per 128-row X tile

// smem layout (bytes)
#define SM_H    0                        // 128KB h1 tile: 8 blocks of [128 rows][64 k]
#define SM_A    131072                   // 2 x 16KB A staging
#define SM_B    (SM_A + 2 * A_BLK)       // 2 x 32KB B staging
#define SM_QS   SM_A                     // reuse A staging for final reduce (2KB)
#define SMEM_TOTAL (SM_B + 2 * B_SL)     // 229376

// ---------------- device global scratch --------------------------------------
__device__ __align__(128) __half g_Xh [(size_t)ROWS * KQ1];    // X, A-layout fp16
__device__ __align__(128) __half g_W1Q[(size_t)EMBED * KQ1];   // weights, B-layout [N][K]
__device__ __align__(128) __half g_W2Q[(size_t)EMBED * EMBED];
__device__ __align__(128) __half g_W1V[(size_t)EMBED * EMBED];
__device__ __align__(128) __half g_W2V[(size_t)EMBED * EMBED];

// ---------------- helpers -----------------------------------------------------
__device__ __forceinline__ uint32_t swz(uint32_t b) { return b ^ ((b >> 3) & 0x70); }

__device__ __forceinline__ uint32_t smem_u32(const void* p) {
    uint32_t a;
    asm("{ .reg .u64 t; cvta.to.shared.u64 t, %1; cvt.u32.u64 %0, t; }" : "=r"(a) : "l"(p));
    return a;
}

__device__ __forceinline__ void cp16(uint32_t dst, const void* src) {
    asm volatile("cp.async.cg.shared.global [%0], [%1], 16;" :: "r"(dst), "l"(src));
}
#define CP_COMMIT() asm volatile("cp.async.commit_group;")
#define CP_WAIT(n)  asm volatile("cp.async.wait_group %0;" :: "n"(n))

__device__ __forceinline__ void ldsm4(uint32_t& r0, uint32_t& r1, uint32_t& r2, uint32_t& r3,
                                      uint32_t addr) {
    asm volatile("ldmatrix.sync.aligned.m8n8.x4.shared.b16 {%0,%1,%2,%3}, [%4];"
                 : "=r"(r0), "=r"(r1), "=r"(r2), "=r"(r3) : "r"(addr));
}

__device__ __forceinline__ void mma16816(float* c, const uint32_t* a, const uint32_t* b) {
    asm volatile(
        "mma.sync.aligned.m16n8k16.row.col.f32.f16.f16.f32 "
        "{%0,%1,%2,%3}, {%4,%5,%6,%7}, {%8,%9}, {%0,%1,%2,%3};"
        : "+f"(c[0]), "+f"(c[1]), "+f"(c[2]), "+f"(c[3])
        : "r"(a[0]), "r"(a[1]), "r"(a[2]), "r"(a[3]), "r"(b[0]), "r"(b[1]));
}

// ---------------- prep kernels ------------------------------------------------
__global__ void prep_weights(const float* __restrict__ Qw1, const float* __restrict__ Qw2,
                             const float* __restrict__ Vw1, const float* __restrict__ Vw2) {
    size_t idx = (size_t)blockIdx.x * blockDim.x + threadIdx.x;
    const float* src; __half* dst;
    size_t off = idx;
    if (off < (size_t)KQ1 * EMBED) { src = Qw1; dst = g_W1Q; }
    else {
        off -= (size_t)KQ1 * EMBED;
        if (off < (size_t)EMBED * EMBED) { src = Qw2; dst = g_W2Q; }
        else {
            off -= (size_t)EMBED * EMBED;
            if (off < (size_t)EMBED * EMBED) { src = Vw1; dst = g_W1V; }
            else {
                off -= (size_t)EMBED * EMBED;
                if (off >= (size_t)EMBED * EMBED) return;
                src = Vw2; dst = g_W2V;
            }
        }
    }
    size_t k = off / EMBED, n = off % EMBED;
    float v = src[k * EMBED + n];
    size_t b = k >> 6; uint32_t kk = (uint32_t)(k & 63);
    char* p = (char*)dst + b * (size_t)B_BLKF + swz((uint32_t)(n * 128 + kk * 2));
    *(__half*)p = __float2half_rn(v);
}

__global__ void prep_x(const float* __restrict__ states, const float* __restrict__ actions) {
    size_t idx = (size_t)blockIdx.x * blockDim.x + threadIdx.x;  // ROWS*512 half2 pairs
    if (idx >= (size_t)ROWS * 512) return;
    size_t r = idx >> 9;
    int k = ((int)(idx & 511)) * 2;
    float2 v;
    if (k < 512) v = *(const float2*)(states + r * 512 + k);
    else         v = *(const float2*)(actions + r * 512 + (k - 512));
    __half2 h = __floats2half2_rn(v.x, v.y);
    size_t t = r >> 7; int rr = (int)(r & 127);
    int b = k >> 6, kk = k & 63;
    char* p = (char*)g_Xh + t * (size_t)XTILE + (size_t)b * A_BLK
              + swz((uint32_t)(rr * 128 + kk * 2));
    *(__half2*)p = h;
}

// ---------------- main-kernel building blocks ---------------------------------
__device__ __forceinline__ void compute_chunk(uint32_t a_base, uint32_t b_base,
                                              float acc[4][8][4], int lane,
                                              int nbase, int mbase) {
    int l16 = lane & 15;
    int ahalf = (lane >= 16) ? 8 : 0;
    int l8 = lane & 7;
    int q  = lane >> 3;
    int bn = ((q >= 2) ? 8 : 0) + l8;
    int bk = (q & 1) ? 8 : 0;
    #pragma unroll
    for (int s = 0; s < 4; s++) {
        uint32_t a[4][4];
        #pragma unroll
        for (int i = 0; i < 4; i++) {
            int row = mbase + i * 16 + l16;
            int col = s * 16 + ahalf;
            ldsm4(a[i][0], a[i][1], a[i][2], a[i][3], a_base + swz(row * 128 + col * 2));
        }
        uint32_t b[4][4];
        #pragma unroll
        for (int p = 0; p < 4; p++) {
            int n = nbase + p * 16 + bn;
            int k = s * 16 + bk;
            ldsm4(b[p][0], b[p][1], b[p][2], b[p][3], b_base + swz(n * 128 + k * 2));
        }
        #pragma unroll
        for (int i = 0; i < 4; i++)
            #pragma unroll
            for (int j = 0; j < 8; j++)
                mma16816(acc[i][j], a[i], &b[j >> 1][(j & 1) * 2]);
    }
}

// Layer-1 pass: A streamed from global, B slice streamed.
// Race-free 1-barrier protocol: WAIT(0) -> sync -> issue prefetch -> compute.
__device__ void gemm_l1(const char* __restrict__ Ag, const char* __restrict__ Bg, int nkb,
                        uint32_t sb, float acc[4][8][4], int tid, int lane,
                        int nbase, int mbase) {
    __syncthreads();   // prior consumers of staging buffers are done
    for (int i = tid; i < 1024; i += THREADS) cp16(sb + SM_A + i * 16, Ag + i * 16);
    for (int i = tid; i < 2048; i += THREADS) cp16(sb + SM_B + i * 16, Bg + i * 16);
    CP_COMMIT();
    for (int kb = 0; kb < nkb; kb++) {
        int cur = kb & 1;
        CP_WAIT(0);        // my copies for cur landed
        __syncthreads();   // everyone's copies landed; everyone done with prev compute
        if (kb + 1 < nkb) {
            int nxt = cur ^ 1;
            const char* a = Ag + (size_t)(kb + 1) * A_BLK;
            const char* b = Bg + (size_t)(kb + 1) * B_BLKF;
            for (int i = tid; i < 1024; i += THREADS) cp16(sb + SM_A + nxt * A_BLK + i * 16, a + i * 16);
            for (int i = tid; i < 2048; i += THREADS) cp16(sb + SM_B + nxt * B_SL + i * 16, b + i * 16);
            CP_COMMIT();
        }
        compute_chunk(sb + SM_A + cur * A_BLK, sb + SM_B + cur * B_SL, acc, lane, nbase, mbase);
    }
}

// Layer-2 pass: A = h1 resident in smem (SM_H), B slice streamed.
__device__ void gemm_l2(const char* __restrict__ Bg, int nkb, uint32_t sb,
                        float acc[4][8][4], int tid, int lane, int nbase, int mbase) {
    __syncthreads();   // epi_mid writes to SM_H published; staging free
    for (int i = tid; i < 2048; i += THREADS) cp16(sb + SM_B + i * 16, Bg + i * 16);
    CP_COMMIT();
    for (int kb = 0; kb < nkb; kb++) {
        int cur = kb & 1;
        CP_WAIT(0);
        __syncthreads();
        if (kb + 1 < nkb) {
            int nxt = cur ^ 1;
            const char* b = Bg + (size_t)(kb + 1) * B_BLKF;
            for (int i = tid; i < 2048; i += THREADS) cp16(sb + SM_B + nxt * B_SL + i * 16, b + i * 16);
            CP_COMMIT();
        }
        compute_chunk(sb + SM_H + kb * A_BLK, sb + SM_B + cur * B_SL, acc, lane, nbase, mbase);
    }
}

// bias + relu -> h1 (fp16) into smem H (blocked A-layout for layer 2)
__device__ void epi_mid(float acc[4][8][4], const float* __restrict__ bias,
                        char* __restrict__ smem, int lane, int warp, int pass) {
    int g = lane >> 2, tig = lane & 3;
    int mhalf = warp >> 2, nq = warp & 3;
    #pragma unroll
    for (int j = 0; j < 8; j++) {
        int c = pass * 256 + nq * 64 + j * 8 + tig * 2;
        float b0 = bias[c], b1 = bias[c + 1];
        int blk = c >> 6, kk = c & 63;
        char* base = smem + SM_H + blk * A_BLK;
        #pragma unroll
        for (int i = 0; i < 4; i++) {
            float v0 = fmaxf(acc[i][j][0] + b0, 0.f);
            float v1 = fmaxf(acc[i][j][1] + b1, 0.f);
            float v2 = fmaxf(acc[i][j][2] + b0, 0.f);
            float v3 = fmaxf(acc[i][j][3] + b1, 0.f);
            int r0 = mhalf * 64 + i * 16 + g, r1 = r0 + 8;
            *(__half2*)(base + swz((uint32_t)(r0 * 128 + kk * 2))) = __floats2half2_rn(v0, v1);
            *(__half2*)(base + swz((uint32_t)(r1 * 128 + kk * 2))) = __floats2half2_rn(v2, v3);
        }
    }
}

// bias + relu + dot(w3) partial over this pass's 256 cols; accumulate into pf[8]
__device__ void epi_fin_partial(float acc[4][8][4], const float* __restrict__ bias,
                                const float* __restrict__ w3, int pass,
                                float pf[8], int lane, int warp) {
    int tig = lane & 3;
    int nq = warp & 3;
    #pragma unroll
    for (int j = 0; j < 8; j++) {
        int c = pass * 256 + nq * 64 + j * 8 + tig * 2;
        float b0 = bias[c], b1 = bias[c + 1];
        float w0 = w3[c],  w1 = w3[c + 1];
        #pragma unroll
        for (int i = 0; i < 4; i++) {
            pf[i * 2 + 0] += fmaxf(acc[i][j][0] + b0, 0.f) * w0 + fmaxf(acc[i][j][1] + b1, 0.f) * w1;
            pf[i * 2 + 1] += fmaxf(acc[i][j][2] + b0, 0.f) * w0 + fmaxf(acc[i][j][3] + b1, 0.f) * w1;
        }
    }
}

// reduce pf across lanes/warps and write out[128]
__device__ void epi_fin_write(float pf[8], const float* __restrict__ b3g,
                              char* __restrict__ smem, float* __restrict__ outp,
                              int lane, int warp, int tid) {
    int g = lane >> 2, tig = lane & 3;
    int mhalf = warp >> 2, nq = warp & 3;
    #pragma unroll
    for (int k = 0; k < 8; k++) {
        pf[k] += __shfl_xor_sync(0xffffffffu, pf[k], 1);
        pf[k] += __shfl_xor_sync(0xffffffffu, pf[k], 2);
    }
    __syncthreads();   // last gemm_l2 compute done everywhere before reusing SM_QS(=SM_A)
    float* qs = (float*)(smem + SM_QS);   // [4][128]
    if (tig == 0) {
        #pragma unroll
        for (int i = 0; i < 4; i++) {
            int r0 = mhalf * 64 + i * 16 + g;
            qs[nq * 128 + r0]     = pf[i * 2 + 0];
            qs[nq * 128 + r0 + 8] = pf[i * 2 + 1];
        }
    }
    __syncthreads();
    if (tid < 128) {
        float s = b3g[0];
        #pragma unroll
        for (int q = 0; q < 4; q++) s += qs[q * 128 + tid];
        outp[tid] = s;
    }
}

__device__ __forceinline__ void zero_acc(float acc[4][8][4]) {
    #pragma unroll
    for (int i = 0; i < 4; i++)
        #pragma unroll
        for (int j = 0; j < 8; j++)
            #pragma unroll
            for (int e = 0; e < 4; e++) acc[i][j][e] = 0.f;
}

// ---------------- fused main kernel -------------------------------------------
__global__ void __launch_bounds__(THREADS, 1)
fused_mlp(const float* __restrict__ b1Q, const float* __restrict__ b2Q,
          const float* __restrict__ w3Q, const float* __restrict__ b3Q,
          const float* __restrict__ b1V, const float* __restrict__ b2V,
          const float* __restrict__ w3V, const float* __restrict__ b3V,
          float* __restrict__ out) {
    extern __shared__ __align__(1024) char smem[];
    uint32_t sb = smem_u32(smem);
    int tid = threadIdx.x, lane = tid & 31, warp = tid >> 5;
    int mbase = (warp >> 2) * 64;
    int nbase = (warp & 3) * 64;

    for (int t = blockIdx.x; t < NTILES; t += GRID) {
        const char* Xt = (const char*)g_Xh + (size_t)t * XTILE;
        float acc[4][8][4];

        // ---- Q network ----
        #pragma unroll
        for (int pass = 0; pass < 2; pass++) {
            zero_acc(acc);
            gemm_l1(Xt, (const char*)g_W1Q + pass * B_SL, 16, sb, acc, tid, lane, nbase, mbase);
            epi_mid(acc, b1Q, smem, lane, warp, pass);
        }
        {
            float pf[8] = {0.f, 0.f, 0.f, 0.f, 0.f, 0.f, 0.f, 0.f};
            #pragma unroll
            for (int pass = 0; pass < 2; pass++) {
                zero_acc(acc);
                gemm_l2((const char*)g_W2Q + pass * B_SL, 8, sb, acc, tid, lane, nbase, mbase);
                epi_fin_partial(acc, b2Q, w3Q, pass, pf, lane, warp);
            }
            epi_fin_write(pf, b3Q, smem, out + (size_t)t * MT, lane, warp, tid);
        }

        // ---- V network (states = first 8 K-blocks of X) ----
        #pragma unroll
        for (int pass = 0; pass < 2; pass++) {
            zero_acc(acc);
            gemm_l1(Xt, (const char*)g_W1V + pass * B_SL, 8, sb, acc, tid, lane, nbase, mbase);
            epi_mid(acc, b1V, smem, lane, warp, pass);
        }
        {
            float pf[8] = {0.f, 0.f, 0.f, 0.f, 0.f, 0.f, 0.f, 0.f};
            #pragma unroll
            for (int pass = 0; pass < 2; pass++) {
                zero_acc(acc);
                gemm_l2((const char*)g_W2V + pass * B_SL, 8, sb, acc, tid, lane, nbase, mbase);
                epi_fin_partial(acc, b2V, w3V, pass, pf, lane, warp);
            }
            epi_fin_write(pf, b3V, smem, out + ROWS + (size_t)t * MT, lane, warp, tid);
        }
    }
}

// ---------------- launch -------------------------------------------------------
extern "C" void kernel_launch(void* const* d_in, const int* in_sizes, int n_in,
                              void* d_out, int out_size) {
    const float* states  = (const float*)d_in[0];
    const float* actions = (const float*)d_in[1];
    const float* Qw1 = (const float*)d_in[2];  const float* Qb1 = (const float*)d_in[3];
    const float* Qw2 = (const float*)d_in[4];  const float* Qb2 = (const float*)d_in[5];
    const float* Qw3 = (const float*)d_in[6];  const float* Qb3 = (const float*)d_in[7];
    const float* Vw1 = (const float*)d_in[8];  const float* Vb1 = (const float*)d_in[9];
    const float* Vw2 = (const float*)d_in[10]; const float* Vb2 = (const float*)d_in[11];
    const float* Vw3 = (const float*)d_in[12]; const float* Vb3 = (const float*)d_in[13];
    float* out = (float*)d_out;

    cudaFuncSetAttribute(fused_mlp, cudaFuncAttributeMaxDynamicSharedMemorySize, SMEM_TOTAL);

    prep_weights<<<5120, 256>>>(Qw1, Qw2, Vw1, Vw2);
    prep_x<<<65536, 256>>>(states, actions);
    fused_mlp<<<GRID, THREADS, SMEM_TOTAL>>>(Qb1, Qb2, Qw3, Qb3, Vb1, Vb2, Vw3, Vb3, out);
}

// round 9
// speedup vs baseline: 1.1426x; 1.1047x over previous
#include <cuda_runtime.h>
#include <cuda_fp16.h>
#include <cstdint>

#define THREADS 256
#define MT      128
#define EMBED   512
#define KQ1     1024
#define ROWS    32768
#define NTILES  (ROWS / MT)     // 256
#define GRID    148
#define NITEMS  (NTILES * 2)    // 512 work items: (tile, network)

#define A_BLK   16384           // 128 rows * 128B (64 fp16 k)
#define B_BLKF  65536           // full K64 weight block (512 n-rows) in global
#define B_SL    32768           // 256 n-row pass slice
#define XTILE   (MT * KQ1 * 2)  // 262144 bytes per 128-row X tile

// smem layout (bytes)
#define SM_H    0                        // 128KB h1 tile: 8 blocks of [128 rows][64 k]
#define SM_A    131072                   // 2 x 16KB A staging
#define SM_B    (SM_A + 2 * A_BLK)       // 2 x 32KB B staging
#define SM_QS   SM_A                     // reuse A staging for final reduce (2KB)
#define SM_ITEM (SM_B + 2 * B_SL)        // 4B work-item broadcast
#define SMEM_TOTAL (SM_ITEM + 16)

// ---------------- device global scratch --------------------------------------
__device__ __align__(128) __half g_Xh [(size_t)ROWS * KQ1];    // X, A-layout fp16
__device__ __align__(128) __half g_W1Q[(size_t)EMBED * KQ1];   // weights, B-layout [N][K]
__device__ __align__(128) __half g_W2Q[(size_t)EMBED * EMBED];
__device__ __align__(128) __half g_W1V[(size_t)EMBED * EMBED];
__device__ __align__(128) __half g_W2V[(size_t)EMBED * EMBED];
__device__ int g_work;

// ---------------- helpers -----------------------------------------------------
__device__ __forceinline__ uint32_t swz(uint32_t b) { return b ^ ((b >> 3) & 0x70); }

__device__ __forceinline__ uint32_t smem_u32(const void* p) {
    uint32_t a;
    asm("{ .reg .u64 t; cvta.to.shared.u64 t, %1; cvt.u32.u64 %0, t; }" : "=r"(a) : "l"(p));
    return a;
}

__device__ __forceinline__ void cp16(uint32_t dst, const void* src) {
    asm volatile("cp.async.cg.shared.global [%0], [%1], 16;" :: "r"(dst), "l"(src));
}
#define CP_COMMIT() asm volatile("cp.async.commit_group;")
#define CP_WAIT(n)  asm volatile("cp.async.wait_group %0;" :: "n"(n))

__device__ __forceinline__ void ldsm4(uint32_t& r0, uint32_t& r1, uint32_t& r2, uint32_t& r3,
                                      uint32_t addr) {
    asm volatile("ldmatrix.sync.aligned.m8n8.x4.shared.b16 {%0,%1,%2,%3}, [%4];"
                 : "=r"(r0), "=r"(r1), "=r"(r2), "=r"(r3) : "r"(addr));
}

__device__ __forceinline__ void mma16816(float* c, const uint32_t* a, const uint32_t* b) {
    asm volatile(
        "mma.sync.aligned.m16n8k16.row.col.f32.f16.f16.f32 "
        "{%0,%1,%2,%3}, {%4,%5,%6,%7}, {%8,%9}, {%0,%1,%2,%3};"
        : "+f"(c[0]), "+f"(c[1]), "+f"(c[2]), "+f"(c[3])
        : "r"(a[0]), "r"(a[1]), "r"(a[2]), "r"(a[3]), "r"(b[0]), "r"(b[1]));
}

// ---------------- merged prep kernel ------------------------------------------
// Part 1 (idx < N_XG): X conversion, 8 k-elems (16B) per thread, vectorized.
// Part 2: weight conversion (scalar scatter, small).
#define N_XG (ROWS * 128)                 // 4,194,304 16B-groups
#define N_W  (KQ1 * EMBED + 3 * EMBED * EMBED)  // 1,310,720
#define PREP_BLOCKS ((N_XG + N_W) / 256)  // 21504

__global__ void prep_all(const float* __restrict__ states, const float* __restrict__ actions,
                         const float* __restrict__ Qw1, const float* __restrict__ Qw2,
                         const float* __restrict__ Vw1, const float* __restrict__ Vw2) {
    size_t idx = (size_t)blockIdx.x * blockDim.x + threadIdx.x;
    if (idx == 0) g_work = 0;   // reset work queue for the following fused launch
    if (idx < (size_t)N_XG) {
        size_t r = idx >> 7;
        int kg = ((int)(idx & 127)) * 8;
        const float* src = (kg < 512) ? (states + r * 512 + kg)
                                      : (actions + r * 512 + (kg - 512));
        float4 v0 = *(const float4*)src;
        float4 v1 = *(const float4*)(src + 4);
        __half2 h0 = __floats2half2_rn(v0.x, v0.y);
        __half2 h1 = __floats2half2_rn(v0.z, v0.w);
        __half2 h2 = __floats2half2_rn(v1.x, v1.y);
        __half2 h3 = __floats2half2_rn(v1.z, v1.w);
        uint4 o;
        o.x = *(uint32_t*)&h0; o.y = *(uint32_t*)&h1;
        o.z = *(uint32_t*)&h2; o.w = *(uint32_t*)&h3;
        size_t t = r >> 7; int rr = (int)(r & 127);
        int b = kg >> 6, kk = kg & 63;
        char* p = (char*)g_Xh + t * (size_t)XTILE + (size_t)b * A_BLK
                  + swz((uint32_t)(rr * 128 + kk * 2));
        *(uint4*)p = o;
        return;
    }
    size_t off = idx - N_XG;
    const float* src; __half* dst;
    if (off < (size_t)KQ1 * EMBED) { src = Qw1; dst = g_W1Q; }
    else {
        off -= (size_t)KQ1 * EMBED;
        if (off < (size_t)EMBED * EMBED) { src = Qw2; dst = g_W2Q; }
        else {
            off -= (size_t)EMBED * EMBED;
            if (off < (size_t)EMBED * EMBED) { src = Vw1; dst = g_W1V; }
            else {
                off -= (size_t)EMBED * EMBED;
                if (off >= (size_t)EMBED * EMBED) return;
                src = Vw2; dst = g_W2V;
            }
        }
    }
    size_t k = off / EMBED, n = off % EMBED;
    float v = src[k * EMBED + n];
    size_t b = k >> 6; uint32_t kk = (uint32_t)(k & 63);
    char* p = (char*)dst + b * (size_t)B_BLKF + swz((uint32_t)(n * 128 + kk * 2));
    *(__half*)p = __float2half_rn(v);
}

// ---------------- main-kernel building blocks ---------------------------------
__device__ __forceinline__ void compute_chunk(uint32_t a_base, uint32_t b_base,
                                              float acc[4][8][4], int lane,
                                              int nbase, int mbase) {
    int l16 = lane & 15;
    int ahalf = (lane >= 16) ? 8 : 0;
    int l8 = lane & 7;
    int q  = lane >> 3;
    int bn = ((q >= 2) ? 8 : 0) + l8;
    int bk = (q & 1) ? 8 : 0;
    #pragma unroll
    for (int s = 0; s < 4; s++) {
        uint32_t a[4][4];
        #pragma unroll
        for (int i = 0; i < 4; i++) {
            int row = mbase + i * 16 + l16;
            int col = s * 16 + ahalf;
            ldsm4(a[i][0], a[i][1], a[i][2], a[i][3], a_base + swz(row * 128 + col * 2));
        }
        uint32_t b[4][4];
        #pragma unroll
        for (int p = 0; p < 4; p++) {
            int n = nbase + p * 16 + bn;
            int k = s * 16 + bk;
            ldsm4(b[p][0], b[p][1], b[p][2], b[p][3], b_base + swz(n * 128 + k * 2));
        }
        #pragma unroll
        for (int i = 0; i < 4; i++)
            #pragma unroll
            for (int j = 0; j < 8; j++)
                mma16816(acc[i][j], a[i], &b[j >> 1][(j & 1) * 2]);
    }
}

// Layer-1 pass: A streamed from global, B slice streamed.
// Race-free 1-barrier protocol: WAIT(0) -> sync -> issue prefetch -> compute.
__device__ void gemm_l1(const char* __restrict__ Ag, const char* __restrict__ Bg, int nkb,
                        uint32_t sb, float acc[4][8][4], int tid, int lane,
                        int nbase, int mbase) {
    __syncthreads();   // prior consumers of staging buffers / SM_H writers are done
    for (int i = tid; i < 1024; i += THREADS) cp16(sb + SM_A + i * 16, Ag + i * 16);
    for (int i = tid; i < 2048; i += THREADS) cp16(sb + SM_B + i * 16, Bg + i * 16);
    CP_COMMIT();
    for (int kb = 0; kb < nkb; kb++) {
        int cur = kb & 1;
        CP_WAIT(0);        // my copies for cur landed
        __syncthreads();   // everyone's copies landed; everyone done with prev compute
        if (kb + 1 < nkb) {
            int nxt = cur ^ 1;
            const char* a = Ag + (size_t)(kb + 1) * A_BLK;
            const char* b = Bg + (size_t)(kb + 1) * B_BLKF;
            for (int i = tid; i < 1024; i += THREADS) cp16(sb + SM_A + nxt * A_BLK + i * 16, a + i * 16);
            for (int i = tid; i < 2048; i += THREADS) cp16(sb + SM_B + nxt * B_SL + i * 16, b + i * 16);
            CP_COMMIT();
        }
        compute_chunk(sb + SM_A + cur * A_BLK, sb + SM_B + cur * B_SL, acc, lane, nbase, mbase);
    }
}

// Layer-2 pass: A = h1 resident in smem (SM_H), B slice streamed.
__device__ void gemm_l2(const char* __restrict__ Bg, int nkb, uint32_t sb,
                        float acc[4][8][4], int tid, int lane, int nbase, int mbase) {
    __syncthreads();   // epi_mid writes to SM_H published; staging free
    for (int i = tid; i < 2048; i += THREADS) cp16(sb + SM_B + i * 16, Bg + i * 16);
    CP_COMMIT();
    for (int kb = 0; kb < nkb; kb++) {
        int cur = kb & 1;
        CP_WAIT(0);
        __syncthreads();
        if (kb + 1 < nkb) {
            int nxt = cur ^ 1;
            const char* b = Bg + (size_t)(kb + 1) * B_BLKF;
            for (int i = tid; i < 2048; i += THREADS) cp16(sb + SM_B + nxt * B_SL + i * 16, b + i * 16);
            CP_COMMIT();
        }
        compute_chunk(sb + SM_H + kb * A_BLK, sb + SM_B + cur * B_SL, acc, lane, nbase, mbase);
    }
}

// bias + relu -> h1 (fp16) into smem H (blocked A-layout for layer 2)
__device__ void epi_mid(float acc[4][8][4], const float* __restrict__ bias,
                        char* __restrict__ smem, int lane, int warp, int pass) {
    int g = lane >> 2, tig = lane & 3;
    int mhalf = warp >> 2, nq = warp & 3;
    #pragma unroll
    for (int j = 0; j < 8; j++) {
        int c = pass * 256 + nq * 64 + j * 8 + tig * 2;
        float b0 = bias[c], b1 = bias[c + 1];
        int blk = c >> 6, kk = c & 63;
        char* base = smem + SM_H + blk * A_BLK;
        #pragma unroll
        for (int i = 0; i < 4; i++) {
            float v0 = fmaxf(acc[i][j][0] + b0, 0.f);
            float v1 = fmaxf(acc[i][j][1] + b1, 0.f);
            float v2 = fmaxf(acc[i][j][2] + b0, 0.f);
            float v3 = fmaxf(acc[i][j][3] + b1, 0.f);
            int r0 = mhalf * 64 + i * 16 + g, r1 = r0 + 8;
            *(__half2*)(base + swz((uint32_t)(r0 * 128 + kk * 2))) = __floats2half2_rn(v0, v1);
            *(__half2*)(base + swz((uint32_t)(r1 * 128 + kk * 2))) = __floats2half2_rn(v2, v3);
        }
    }
}

// bias + relu + dot(w3) partial over this pass's 256 cols; accumulate into pf[8]
__device__ void epi_fin_partial(float acc[4][8][4], const float* __restrict__ bias,
                                const float* __restrict__ w3, int pass,
                                float pf[8], int lane, int warp) {
    int tig = lane & 3;
    int nq = warp & 3;
    #pragma unroll
    for (int j = 0; j < 8; j++) {
        int c = pass * 256 + nq * 64 + j * 8 + tig * 2;
        float b0 = bias[c], b1 = bias[c + 1];
        float w0 = w3[c],  w1 = w3[c + 1];
        #pragma unroll
        for (int i = 0; i < 4; i++) {
            pf[i * 2 + 0] += fmaxf(acc[i][j][0] + b0, 0.f) * w0 + fmaxf(acc[i][j][1] + b1, 0.f) * w1;
            pf[i * 2 + 1] += fmaxf(acc[i][j][2] + b0, 0.f) * w0 + fmaxf(acc[i][j][3] + b1, 0.f) * w1;
        }
    }
}

// reduce pf across lanes/warps and write out[128]
__device__ void epi_fin_write(float pf[8], const float* __restrict__ b3g,
                              char* __restrict__ smem, float* __restrict__ outp,
                              int lane, int warp, int tid) {
    int g = lane >> 2, tig = lane & 3;
    int mhalf = warp >> 2, nq = warp & 3;
    #pragma unroll
    for (int k = 0; k < 8; k++) {
        pf[k] += __shfl_xor_sync(0xffffffffu, pf[k], 1);
        pf[k] += __shfl_xor_sync(0xffffffffu, pf[k], 2);
    }
    __syncthreads();   // last gemm_l2 compute done everywhere before reusing SM_QS(=SM_A)
    float* qs = (float*)(smem + SM_QS);   // [4][128]
    if (tig == 0) {
        #pragma unroll
        for (int i = 0; i < 4; i++) {
            int r0 = mhalf * 64 + i * 16 + g;
            qs[nq * 128 + r0]     = pf[i * 2 + 0];
            qs[nq * 128 + r0 + 8] = pf[i * 2 + 1];
        }
    }
    __syncthreads();
    if (tid < 128) {
        float s = b3g[0];
        #pragma unroll
        for (int q = 0; q < 4; q++) s += qs[q * 128 + tid];
        outp[tid] = s;
    }
}

__device__ __forceinline__ void zero_acc(float acc[4][8][4]) {
    #pragma unroll
    for (int i = 0; i < 4; i++)
        #pragma unroll
        for (int j = 0; j < 8; j++)
            #pragma unroll
            for (int e = 0; e < 4; e++) acc[i][j][e] = 0.f;
}

// ---------------- fused main kernel -------------------------------------------
__global__ void __launch_bounds__(THREADS, 1)
fused_mlp(const float* __restrict__ b1Q, const float* __restrict__ b2Q,
          const float* __restrict__ w3Q, const float* __restrict__ b3Q,
          const float* __restrict__ b1V, const float* __restrict__ b2V,
          const float* __restrict__ w3V, const float* __restrict__ b3V,
          float* __restrict__ out) {
    extern __shared__ __align__(1024) char smem[];
    uint32_t sb = smem_u32(smem);
    int tid = threadIdx.x, lane = tid & 31, warp = tid >> 5;
    int mbase = (warp >> 2) * 64;
    int nbase = (warp & 3) * 64;

    for (;;) {
        if (tid == 0) *(volatile int*)(smem + SM_ITEM) = atomicAdd(&g_work, 1);
        __syncthreads();
        int item = *(volatile int*)(smem + SM_ITEM);
        if (item >= NITEMS) break;

        int t   = item >> 1;          // tile
        int net = item & 1;           // 0 = Q, 1 = V (adjacent -> shared X tile in L2)
        const char* Xt = (const char*)g_Xh + (size_t)t * XTILE;
        const char* W1 = net ? (const char*)g_W1V : (const char*)g_W1Q;
        const char* W2 = net ? (const char*)g_W2V : (const char*)g_W2Q;
        const float* b1 = net ? b1V : b1Q;
        const float* b2 = net ? b2V : b2Q;
        const float* w3 = net ? w3V : w3Q;
        const float* b3 = net ? b3V : b3Q;
        int nkb1 = net ? 8 : 16;
        float* outp = out + (size_t)net * ROWS + (size_t)t * MT;

        float acc[4][8][4];

        #pragma unroll
        for (int pass = 0; pass < 2; pass++) {
            zero_acc(acc);
            gemm_l1(Xt, W1 + pass * B_SL, nkb1, sb, acc, tid, lane, nbase, mbase);
            epi_mid(acc, b1, smem, lane, warp, pass);
        }
        {
            float pf[8] = {0.f, 0.f, 0.f, 0.f, 0.f, 0.f, 0.f, 0.f};
            #pragma unroll
            for (int pass = 0; pass < 2; pass++) {
                zero_acc(acc);
                gemm_l2(W2 + pass * B_SL, 8, sb, acc, tid, lane, nbase, mbase);
                epi_fin_partial(acc, b2, w3, pass, pf, lane, warp);
            }
            epi_fin_write(pf, b3, smem, outp, lane, warp, tid);
        }
    }
}

// ---------------- launch -------------------------------------------------------
extern "C" void kernel_launch(void* const* d_in, const int* in_sizes, int n_in,
                              void* d_out, int out_size) {
    const float* states  = (const float*)d_in[0];
    const float* actions = (const float*)d_in[1];
    const float* Qw1 = (const float*)d_in[2];  const float* Qb1 = (const float*)d_in[3];
    const float* Qw2 = (const float*)d_in[4];  const float* Qb2 = (const float*)d_in[5];
    const float* Qw3 = (const float*)d_in[6];  const float* Qb3 = (const float*)d_in[7];
    const float* Vw1 = (const float*)d_in[8];  const float* Vb1 = (const float*)d_in[9];
    const float* Vw2 = (const float*)d_in[10]; const float* Vb2 = (const float*)d_in[11];
    const float* Vw3 = (const float*)d_in[12]; const float* Vb3 = (const float*)d_in[13];
    float* out = (float*)d_out;

    cudaFuncSetAttribute(fused_mlp, cudaFuncAttributeMaxDynamicSharedMemorySize, SMEM_TOTAL);

    prep_all<<<PREP_BLOCKS, 256>>>(states, actions, Qw1, Qw2, Vw1, Vw2);
    fused_mlp<<<GRID, THREADS, SMEM_TOTAL>>>(Qb1, Qb2, Qw3, Qb3, Vb1, Vb2, Vw3, Vb3, out);
}